// round 10
// baseline (speedup 1.0000x reference)
#include <cuda_runtime.h>
#include <cstdint>

// FlowNetC correlation: B=4, C=128, H=W=96, md=20, stride2=2, K=1, S1=1.
// out[b, iy*21+ix, y, x] = (1/128)*sum_c in1[b,c,y,x]*in2[b,c,y+dy,x+dx]
// dy=(iy-10)*2, dx=(ix-10)*2, zero outside [0,96).
//
// Thread tile: 7 dx x 16 contiguous x (acc in 56 f32x2 regs). Per channel:
// 4 LDS.128 q (warp-broadcast heavy) + 7 LDS.128 k feed 56 fma.rn.f32x2.
// K rows duplicated (copy B shifted left 2 floats) so dxg=1 windows are
// float4-aligned. 128 threads (126 active), 2 blocks/SM.

#define ND 21
#define NDD 441
#define CH 128
#define HH 96
#define WW 96
#define DYG 7
#define CCK 8
#define NCHUNK 16
#define QSTP 104              // Q row stride (floats)
#define KX 144                // K row: [0..19]=0, [20..115]=data, rest 0
#define KROW 1160             // 8*KX + 8 ; 4640B == 32 mod 128 (dyg slot spread)
#define ABASEF 864            // copy A base (floats), 3456B
#define BBASEF 8996           // copy B base (floats), 35984B (==16 mod 128)
#define SMEMF (BBASEF + 7*KROW)   // 17116 floats
#define SMEMB (SMEMF*4)           // 68464 B
#define NT 128
#define NACT 126              // 7 dyg * 3 dxg * 6 xg

typedef unsigned long long u64;

__device__ __forceinline__ u64 ffma2(u64 a, u64 b, u64 c) {
    u64 d;
    asm("fma.rn.f32x2 %0, %1, %2, %3;" : "=l"(d) : "l"(a), "l"(b), "l"(c));
    return d;
}

__global__ void __launch_bounds__(NT, 2)
corr_kernel(const float* __restrict__ in1, const float* __restrict__ in2,
            float* __restrict__ out)
{
    extern __shared__ float smem[];
    float* Qs  = smem;              // [8][QSTP]
    float* KsA = smem + ABASEF;     // [7][8][KX]
    float* KsB = smem + BBASEF;     // same, elements shifted: B[l] = elem(l+2)

    const int y   = blockIdx.x;
    const int b   = blockIdx.y;
    const int p   = blockIdx.z;     // dy rows p*7 .. p*7+6
    const int tid = threadIdx.x;

    // Zero K region once (logical pads must stay zero)
    for (int i = tid; i < (SMEMF - ABASEF) / 4; i += NT)
        *(float4*)(smem + ABASEF + 4 * i) = make_float4(0.f, 0.f, 0.f, 0.f);

    // Thread tile: (dyg, dxg, xg); x = 16*xg .. 16*xg+15, dx = 2*(7*dxg+j)-20
    const bool active = tid < NACT;
    int dyg = 0, dxg = 0, xg = 0;
    if (active) {
        dyg = tid / 18;
        int r = tid - dyg * 18;
        dxg = r / 6;
        xg  = r - dxg * 6;
    }
    const int x0   = 16 * xg;
    const int koff = 16 * xg + 14 * dxg;   // logical window base (always even)
    // float4-aligned pointer into the right copy (B[l] = elem l+2)
    const float* kbase = ((dxg == 1) ? (KsB + koff - 2) : (KsA + koff))
                       + dyg * KROW;
    const float* qbase = Qs + x0;

    u64 acc2[7][8];
    #pragma unroll
    for (int j = 0; j < 7; ++j)
        #pragma unroll
        for (int m = 0; m < 8; ++m) acc2[j][m] = 0ull;

    for (int cc = 0; cc < NCHUNK; ++cc) {
        __syncthreads();   // previous chunk fully consumed
        // ---- Load: 192 Q float4 + 1344 K float4 = 12 tasks/thread ----
        #pragma unroll
        for (int it = 0; it < 12; ++it) {
            int i = tid + it * NT;
            if (i < 192) {
                int c  = i / 24;
                int xq = i - c * 24;
                float4 v = *(const float4*)(in1 +
                    (((size_t)b * CH + cc * CCK + c) * HH + y) * WW + 4 * xq);
                *(float4*)(Qs + c * QSTP + 4 * xq) = v;
            } else {
                int t   = i - 192;
                int r   = t / 192;
                int rem = t - r * 192;
                int c   = rem / 24;
                int xq  = rem - c * 24;
                int yy  = y + (p * DYG + r - 10) * 2;
                float4 v = make_float4(0.f, 0.f, 0.f, 0.f);
                if ((unsigned)yy < HH)
                    v = *(const float4*)(in2 +
                        (((size_t)b * CH + cc * CCK + c) * HH + yy) * WW + 4 * xq);
                int e = 20 + 4 * xq;
                float* ra = KsA + r * KROW + c * KX;
                float* rb = KsB + r * KROW + c * KX;
                *(float4*)(ra + e) = v;
                *(float2*)(rb + e - 2) = make_float2(v.x, v.y);   // B[e-2]=elem e
                *(float2*)(rb + e)     = make_float2(v.z, v.w);   // B[e]  =elem e+2
            }
        }
        __syncthreads();

        if (active) {
            #pragma unroll 1
            for (int c = 0; c < CCK; ++c) {
                const ulonglong2* qp = (const ulonglong2*)(qbase + c * QSTP);
                const ulonglong2* kp = (const ulonglong2*)(kbase + c * KX);
                u64 q2[8], k2[14];
                #pragma unroll
                for (int t = 0; t < 4; ++t) {
                    ulonglong2 v = qp[t];
                    q2[2 * t] = v.x; q2[2 * t + 1] = v.y;
                }
                #pragma unroll
                for (int t = 0; t < 7; ++t) {
                    ulonglong2 v = kp[t];
                    k2[2 * t] = v.x; k2[2 * t + 1] = v.y;
                }
                #pragma unroll
                for (int j = 0; j < 7; ++j)
                    #pragma unroll
                    for (int m = 0; m < 8; ++m)
                        acc2[j][m] = ffma2(q2[m], k2[m + j], acc2[j][m]);
            }
        }
    }

    if (active) {
        const int diy = p * DYG + dyg;
        const float s = 1.0f / 128.0f;
        #pragma unroll
        for (int j = 0; j < 7; ++j) {
            int d = diy * ND + dxg * 7 + j;
            float* o = out + (((size_t)b * NDD + d) * HH + y) * WW + x0;
            #pragma unroll
            for (int m = 0; m < 4; ++m) {
                float2 a0 = *(float2*)&acc2[j][2 * m];
                float2 a1 = *(float2*)&acc2[j][2 * m + 1];
                *(float4*)(o + 4 * m) =
                    make_float4(a0.x * s, a0.y * s, a1.x * s, a1.y * s);
            }
        }
    }
}

extern "C" void kernel_launch(void* const* d_in, const int* in_sizes, int n_in,
                              void* d_out, int out_size)
{
    const float* in1 = (const float*)d_in[0];
    const float* in2 = (const float*)d_in[1];
    float* out = (float*)d_out;

    cudaFuncSetAttribute(corr_kernel,
                         cudaFuncAttributeMaxDynamicSharedMemorySize, SMEMB);
    corr_kernel<<<dim3(HH, 4, 3), NT, SMEMB>>>(in1, in2, out);
}

// round 11
// speedup vs baseline: 2.0590x; 2.0590x over previous
#include <cuda_runtime.h>
#include <cstdint>

// FlowNetC correlation: B=4, C=128, H=W=96, md=20, stride2=2, K=1, S1=1.
// out[b, iy*21+ix, y, x] = (1/128)*sum_c in1[b,c,y,x]*in2[b,c,y+dy,x+dx]
// dy=(iy-10)*2, dx=(ix-10)*2, zero outside [0,96).
//
// Thread tile: 7 dx x 12 contiguous x (acc = 42 f32x2 regs, no spill).
// Per channel: 3 LDS.128 q (warp-dedup) + 12 LDS.64 k feed 42 fma.rn.f32x2.
// Single K copy (no duplicate): k windows are float2-aligned, loaded LDS.64.

#define ND 21
#define NDD 441
#define CH 128
#define HH 96
#define WW 96
#define DYG 7
#define CCK 8
#define NCHUNK 16
#define QSTP 100              // Q row stride (floats)
#define KX 144                // K row: [0..19]=0, [20..115]=data, rest 0
#define KROW 1156             // 8*KX + 4 (mod-32 bank shift of 4 per dy row)
#define ABASEF 864            // K base (floats); Q occupies [0, 800)
#define SMEMF (ABASEF + DYG*KROW)   // 8956 floats
#define SMEMB (SMEMF*4)             // 35824 B
#define NT 192
#define NACT 168              // 7 dyg * 3 dxg * 8 xg

typedef unsigned long long u64;

__device__ __forceinline__ u64 ffma2(u64 a, u64 b, u64 c) {
    u64 d;
    asm("fma.rn.f32x2 %0, %1, %2, %3;" : "=l"(d) : "l"(a), "l"(b), "l"(c));
    return d;
}

__global__ void __launch_bounds__(NT, 2)
corr_kernel(const float* __restrict__ in1, const float* __restrict__ in2,
            float* __restrict__ out)
{
    extern __shared__ float smem[];
    float* Qs = smem;               // [8][QSTP]
    float* Ks = smem + ABASEF;      // [7][8][KX] (+4 stagger per dy row)

    const int y   = blockIdx.x;
    const int b   = blockIdx.y;
    const int p   = blockIdx.z;     // dy rows p*7 .. p*7+6
    const int tid = threadIdx.x;

    // Zero K region once (logical pads stay zero; interior rewritten per chunk)
    for (int i = tid; i < (SMEMF - ABASEF + 3) / 4; i += NT) {
        int o = ABASEF + 4 * i;
        if (o + 4 <= SMEMF) *(float4*)(smem + o) = make_float4(0.f, 0.f, 0.f, 0.f);
    }

    // Thread tile: (dyg, dxg, xg); x = 12*xg .. 12*xg+11, dx = 2*(7*dxg+j)-20
    const bool active = tid < NACT;
    int dyg = 0, dxg = 0, xg = 0;
    if (active) {
        dyg = tid / 24;
        int r = tid - dyg * 24;
        dxg = r / 8;
        xg  = r - dxg * 8;
    }
    const int x0   = 12 * xg;
    const int koff = 12 * xg + 14 * dxg;     // window base (always even)
    const float* kbase = Ks + dyg * KROW + koff;
    const float* qbase = Qs + x0;

    u64 acc2[7][6];
    #pragma unroll
    for (int j = 0; j < 7; ++j)
        #pragma unroll
        for (int n = 0; n < 6; ++n) acc2[j][n] = 0ull;

    for (int cc = 0; cc < NCHUNK; ++cc) {
        __syncthreads();   // previous chunk fully consumed
        // ---- Load: 192 Q float4 + 1344 K float4 = 8 tasks/thread ----
        #pragma unroll
        for (int it = 0; it < 8; ++it) {
            int i = tid + it * NT;
            if (it == 0) {                     // i < 192: Q tasks
                int c  = i / 24;
                int xq = i - c * 24;
                float4 v = *(const float4*)(in1 +
                    (((size_t)b * CH + cc * CCK + c) * HH + y) * WW + 4 * xq);
                *(float4*)(Qs + c * QSTP + 4 * xq) = v;
            } else {
                int t   = i - NT;
                int r   = t / 192;
                int rem = t - r * 192;
                int c   = rem / 24;
                int xq  = rem - c * 24;
                int yy  = y + (p * DYG + r - 10) * 2;
                float4 v = make_float4(0.f, 0.f, 0.f, 0.f);
                if ((unsigned)yy < HH)
                    v = *(const float4*)(in2 +
                        (((size_t)b * CH + cc * CCK + c) * HH + yy) * WW + 4 * xq);
                *(float4*)(Ks + r * KROW + c * KX + 20 + 4 * xq) = v;
            }
        }
        __syncthreads();

        if (active) {
            #pragma unroll 1
            for (int c = 0; c < CCK; ++c) {
                const float* qp = qbase + c * QSTP;
                const float* kp = kbase + c * KX;
                u64 q2[6], k2[12];
                #pragma unroll
                for (int t = 0; t < 3; ++t) {
                    ulonglong2 v = *(const ulonglong2*)(qp + 4 * t);
                    q2[2 * t] = v.x; q2[2 * t + 1] = v.y;
                }
                #pragma unroll
                for (int t = 0; t < 12; ++t)
                    k2[t] = *(const u64*)(kp + 2 * t);
                #pragma unroll
                for (int j = 0; j < 7; ++j)
                    #pragma unroll
                    for (int n = 0; n < 6; ++n)
                        acc2[j][n] = ffma2(q2[n], k2[n + j], acc2[j][n]);
            }
        }
    }

    if (active) {
        const int diy = p * DYG + dyg;
        const float s = 1.0f / 128.0f;
        #pragma unroll
        for (int j = 0; j < 7; ++j) {
            int d = diy * ND + dxg * 7 + j;
            float* o = out + (((size_t)b * NDD + d) * HH + y) * WW + x0;
            #pragma unroll
            for (int m = 0; m < 3; ++m) {
                float2 a0 = *(float2*)&acc2[j][2 * m];
                float2 a1 = *(float2*)&acc2[j][2 * m + 1];
                *(float4*)(o + 4 * m) =
                    make_float4(a0.x * s, a0.y * s, a1.x * s, a1.y * s);
            }
        }
    }
}

extern "C" void kernel_launch(void* const* d_in, const int* in_sizes, int n_in,
                              void* d_out, int out_size)
{
    const float* in1 = (const float*)d_in[0];
    const float* in2 = (const float*)d_in[1];
    float* out = (float*)d_out;

    cudaFuncSetAttribute(corr_kernel,
                         cudaFuncAttributeMaxDynamicSharedMemorySize, SMEMB);
    corr_kernel<<<dim3(HH, 4, 3), NT, SMEMB>>>(in1, in2, out);
}